// round 15
// baseline (speedup 1.0000x reference)
#include <cuda_runtime.h>
#include <cstdint>

#define BB 8
#define NN 8192
#define MM 2048
#define NUM_ITER 4
#define BASE_ALPHA 0.1f
#define BLOCKS_PER_BATCH 64   // NN/128

// Per-iter per-batch max bits + per-iter per-batch arrival counters.
__device__ int g_maxbits[NUM_ITER * BB];
__device__ int g_arrive [NUM_ITER * BB];

// ---------------------------------------------------------------------------
// f32x2 packed helpers (Blackwell FFMA2 path, PTX fma.rn.f32x2)
// ---------------------------------------------------------------------------
__device__ __forceinline__ uint64_t pack2(float lo, float hi) {
    uint64_t r;
    asm("mov.b64 %0, {%1, %2};" : "=l"(r) : "f"(lo), "f"(hi));
    return r;
}
__device__ __forceinline__ uint64_t ffma2(uint64_t a, uint64_t b, uint64_t c) {
    uint64_t d;
    asm("fma.rn.f32x2 %0, %1, %2, %3;" : "=l"(d) : "l"(a), "l"(b), "l"(c));
    return d;
}
__device__ __forceinline__ void unpack2(uint64_t v, float& lo, float& hi) {
    asm("mov.b64 {%0, %1}, %2;" : "=f"(lo), "=f"(hi) : "l"(v));
}

// ---------------------------------------------------------------------------
// Init: zero the max slots and barrier counters.
// ---------------------------------------------------------------------------
__global__ void ipgr_init_kernel() {
    int i = threadIdx.x;
    if (i < NUM_ITER * BB) {
        g_maxbits[i] = 0;
        g_arrive[i]  = 0;
    }
}

// ---------------------------------------------------------------------------
// Persistent NN + refine kernel: all NUM_ITER iterations in one launch.
// Structure identical to the 127.5us R13 kernel (512 co-resident blocks,
// per-batch software barrier, register-resident points), with ONE change:
// the argmin tournament window grows from 4 m's to 16 m's (a group = 4
// k-steps) using a running min accumulator -> per-point update cost drops
// from (FSETP+2SEL) per k-step to once per 4 k-steps (~9% slot saving).
// Index recovery is two-stage, both bit-exact:
//   stage 1: recompute the 4 quad-mins of the winning group with the
//            identical ffma2/fminf sequence, scanning k DESCENDING so the
//            earliest matching k survives;
//   stage 2: scalar 4-position rescan inside that quad (R13-proven),
//            scanning positions 3..0 so the smallest m survives.
// Strict < across groups keeps the earliest group -> exact first-index
// tie-break at every level. Cross-slice/lane merges compare (value, m).
// Lane layout: q = lane>>3 (one of 4 interleaved M-slices, vector v = 4k+q,
// conflict-free LDS); sub = lane&7; 4 points per thread.
// Comparison key: t = |y|^2/2 - x.y (argmin-equivalent; |x|^2 const/point).
// ---------------------------------------------------------------------------
__global__ void __launch_bounds__(128)
ipgr_persist_kernel(const float* __restrict__ pred,
                    const float* __restrict__ partial,
                    float* __restrict__ out) {
    // SoA tile of partial: yx | yy | yz | yh(=0.5*|y|^2), each MM floats.
    __shared__ __align__(16) float sm[4 * MM];
    __shared__ float smax[4];
    __shared__ float s_mx;

    const int b = blockIdx.y;
    const float* p = partial + (size_t)b * MM * 3;

    for (int m = threadIdx.x; m < MM; m += 128) {
        float yx = p[m * 3 + 0];
        float yy = p[m * 3 + 1];
        float yz = p[m * 3 + 2];
        sm[m]          = yx;
        sm[MM + m]     = yy;
        sm[2 * MM + m] = yz;
        sm[3 * MM + m] = 0.5f * fmaf(yz, yz, fmaf(yy, yy, yx * yx));
    }

    const int lane = threadIdx.x & 31;
    const int warp = threadIdx.x >> 5;
    const int q    = lane >> 3;        // 4 interleaved M-slices
    const int sub  = lane & 7;
    const int n0   = blockIdx.x * 128 + warp * 32 + sub * 4;  // 4 points/thread

    // Refined state lives in registers across iterations.
    float x0[4], x1[4], x2[4];
    {
        const float* rp = pred + ((size_t)b * NN + n0) * 3;
#pragma unroll
        for (int i = 0; i < 4; i++) {
            x0[i] = rp[i * 3 + 0];
            x1[i] = rp[i * 3 + 1];
            x2[i] = rp[i * 3 + 2];
        }
    }
    __syncthreads();

    const ulonglong2* pyx = reinterpret_cast<const ulonglong2*>(sm)          + q;
    const ulonglong2* pyy = reinterpret_cast<const ulonglong2*>(sm + MM)     + q;
    const ulonglong2* pyz = reinterpret_cast<const ulonglong2*>(sm + 2 * MM) + q;
    const ulonglong2* pyh = reinterpret_cast<const ulonglong2*>(sm + 3 * MM) + q;

    for (int it = 0; it < NUM_ITER; it++) {
        uint64_t xp0[4], xp1[4], xp2[4];
        float xs[4];
#pragma unroll
        for (int i = 0; i < 4; i++) {
            xp0[i] = pack2(-x0[i], -x0[i]);
            xp1[i] = pack2(-x1[i], -x1[i]);
            xp2[i] = pack2(-x2[i], -x2[i]);
            xs[i]  = fmaf(x2[i], x2[i], fmaf(x1[i], x1[i], x0[i] * x0[i]));
        }

        // Per point: best 16-m group-min value + group index (32 groups).
        float best[4] = {3.4e38f, 3.4e38f, 3.4e38f, 3.4e38f};
        int   bg[4]   = {0, 0, 0, 0};

#pragma unroll 1
        for (int g = 0; g < 32; g++) {
            float gm[4];
#pragma unroll
            for (int kk = 0; kk < 4; kk++) {
                const int k = 4 * g + kk;
                ulonglong2 vx = pyx[4 * k];
                ulonglong2 vy = pyy[4 * k];
                ulonglong2 vz = pyz[4 * k];
                ulonglong2 vh = pyh[4 * k];
#pragma unroll
                for (int i = 0; i < 4; i++) {
                    uint64_t t01 = ffma2(xp0[i], vx.x, vh.x);
                    t01 = ffma2(xp1[i], vy.x, t01);
                    t01 = ffma2(xp2[i], vz.x, t01);
                    uint64_t t23 = ffma2(xp0[i], vx.y, vh.y);
                    t23 = ffma2(xp1[i], vy.y, t23);
                    t23 = ffma2(xp2[i], vz.y, t23);
                    float t0, t1, t2, t3;
                    unpack2(t01, t0, t1);
                    unpack2(t23, t2, t3);
                    float qmin = fminf(fminf(t0, t1), fminf(t2, t3));
                    gm[i] = (kk == 0) ? qmin : fminf(gm[i], qmin);
                }
            }
#pragma unroll
            for (int i = 0; i < 4; i++) {
                bool c = gm[i] < best[i];   // strict: earliest group kept
                best[i] = c ? gm[i] : best[i];
                bg[i]   = c ? g     : bg[i];
            }
        }

        // Stage 1: within the winning group, recompute the 4 quad-mins with
        // the IDENTICAL op sequence; scan k descending -> earliest k wins.
        float bv[4];
        int   bm[4];
#pragma unroll
        for (int i = 0; i < 4; i++) {
            const int g = bg[i];
            int kwin = 4 * g;
#pragma unroll
            for (int kk = 3; kk >= 0; kk--) {
                const int k = 4 * g + kk;
                ulonglong2 vx = pyx[4 * k];
                ulonglong2 vy = pyy[4 * k];
                ulonglong2 vz = pyz[4 * k];
                ulonglong2 vh = pyh[4 * k];
                uint64_t t01 = ffma2(xp0[i], vx.x, vh.x);
                t01 = ffma2(xp1[i], vy.x, t01);
                t01 = ffma2(xp2[i], vz.x, t01);
                uint64_t t23 = ffma2(xp0[i], vx.y, vh.y);
                t23 = ffma2(xp1[i], vy.y, t23);
                t23 = ffma2(xp2[i], vz.y, t23);
                float t0, t1, t2, t3;
                unpack2(t01, t0, t1);
                unpack2(t23, t2, t3);
                float qmin = fminf(fminf(t0, t1), fminf(t2, t3));
                if (qmin == best[i]) kwin = k;
            }
            // Stage 2: scalar rescan of the 4 positions in quad kwin
            // (bit-exact: scalar fma.rn == each f32x2 lane). Scan 3..0.
            const int m0 = (4 * kwin + q) * 4;
            int pos = 3;
#pragma unroll
            for (int j = 2; j >= 0; j--) {
                int mj = m0 + j;
                float tj = fmaf(-x2[i], sm[2 * MM + mj],
                           fmaf(-x1[i], sm[MM + mj],
                           fmaf(-x0[i], sm[mj], sm[3 * MM + mj])));
                if (tj == best[i]) pos = j;
            }
            bv[i] = best[i];
            bm[i] = m0 + pos;
        }

        // Butterfly merge across the 4 slices (bits 3,4): all lanes end with
        // the merged (value, m) for their 4 points. Tie -> smaller m.
#pragma unroll
        for (int r = 8; r <= 16; r <<= 1) {
#pragma unroll
            for (int i = 0; i < 4; i++) {
                float ob = __shfl_xor_sync(0xffffffffu, bv[i], r);
                int   oi = __shfl_xor_sync(0xffffffffu, bm[i], r);
                if (ob < bv[i] || (ob == bv[i] && oi < bm[i])) { bv[i] = ob; bm[i] = oi; }
            }
        }

        // min_dist per point (identical across q-lanes).
        float md[4];
        float mloc = 0.0f;
#pragma unroll
        for (int i = 0; i < 4; i++) {
            float d2 = fmaf(2.0f, bv[i], xs[i]);
            md[i] = sqrtf(fmaxf(d2, 0.0f));
            mloc = fmaxf(mloc, md[i]);
        }

        // Block max -> one atomicMax per block (md >= 0: int order == float).
#pragma unroll
        for (int o = 16; o > 0; o >>= 1)
            mloc = fmaxf(mloc, __shfl_xor_sync(0xffffffffu, mloc, o));
        if (lane == 0) smax[warp] = mloc;
        __syncthreads();

        const int slot = it * BB + b;
        if (threadIdx.x == 0) {
            float m01 = fmaxf(smax[0], smax[1]);
            float m23 = fmaxf(smax[2], smax[3]);
            atomicMax(&g_maxbits[slot], __float_as_int(fmaxf(m01, m23)));
            __threadfence();  // publish max before arrival
            atomicAdd(&g_arrive[slot], 1);
            while (*(volatile int*)&g_arrive[slot] < BLOCKS_PER_BATCH) { }
            __threadfence();
            s_mx = __int_as_float(__ldcg(&g_maxbits[slot]));
        }
        __syncthreads();
        const float mxp = s_mx + 1e-6f;

        // Register-local blend update (all lanes, same result per point).
#pragma unroll
        for (int i = 0; i < 4; i++) {
            int mi = bm[i];
            float alpha = BASE_ALPHA * (2.0f - md[i] / mxp);
            x0[i] = fmaf(alpha, sm[mi]          - x0[i], x0[i]);
            x1[i] = fmaf(alpha, sm[MM + mi]     - x1[i], x1[i]);
            x2[i] = fmaf(alpha, sm[2 * MM + mi] - x2[i], x2[i]);
        }
    }

    // Final store (q==0 lanes own the write; values identical across q).
    if (q == 0) {
        float* rp = out + ((size_t)b * NN + n0) * 3;
#pragma unroll
        for (int i = 0; i < 4; i++) {
            rp[i * 3 + 0] = x0[i];
            rp[i * 3 + 1] = x1[i];
            rp[i * 3 + 2] = x2[i];
        }
    }
}

// ---------------------------------------------------------------------------
extern "C" void kernel_launch(void* const* d_in, const int* in_sizes, int n_in,
                              void* d_out, int out_size) {
    const float* pred    = (const float*)d_in[0];  // [8, 8192, 3] f32
    const float* partial = (const float*)d_in[1];  // [8, 2048, 3] f32
    float* out = (float*)d_out;                     // [8, 8192, 3] f32

    (void)in_sizes; (void)n_in; (void)out_size;

    ipgr_init_kernel<<<1, 64>>>();

    dim3 grid(NN / 128, BB);  // (64, 8) = 512 blocks, all co-resident
    ipgr_persist_kernel<<<grid, 128>>>(pred, partial, out);
}

// round 16
// speedup vs baseline: 1.0931x; 1.0931x over previous
#include <cuda_runtime.h>
#include <cstdint>

#define BB 8
#define NN 8192
#define MM 2048
#define NUM_ITER 4
#define BASE_ALPHA 0.1f
#define BLOCKS_PER_BATCH 64   // NN/128

// Per-iter per-batch max bits + per-iter per-batch arrival counters.
__device__ int g_maxbits[NUM_ITER * BB];
__device__ int g_arrive [NUM_ITER * BB];

// ---------------------------------------------------------------------------
// f32x2 packed helpers (Blackwell FFMA2 path, PTX fma.rn.f32x2)
// ---------------------------------------------------------------------------
__device__ __forceinline__ uint64_t pack2(float lo, float hi) {
    uint64_t r;
    asm("mov.b64 %0, {%1, %2};" : "=l"(r) : "f"(lo), "f"(hi));
    return r;
}
__device__ __forceinline__ uint64_t ffma2(uint64_t a, uint64_t b, uint64_t c) {
    uint64_t d;
    asm("fma.rn.f32x2 %0, %1, %2, %3;" : "=l"(d) : "l"(a), "l"(b), "l"(c));
    return d;
}
__device__ __forceinline__ void unpack2(uint64_t v, float& lo, float& hi) {
    asm("mov.b64 {%0, %1}, %2;" : "=f"(lo), "=f"(hi) : "l"(v));
}

// ---------------------------------------------------------------------------
// Init: zero the max slots and barrier counters.
// ---------------------------------------------------------------------------
__global__ void ipgr_init_kernel() {
    int i = threadIdx.x;
    if (i < NUM_ITER * BB) {
        g_maxbits[i] = 0;
        g_arrive[i]  = 0;
    }
}

// ---------------------------------------------------------------------------
// Persistent NN + refine kernel: all NUM_ITER iterations in one launch.
// EXACT R13 structure (512 co-resident blocks, per-batch software barrier,
// register-resident points, unroll body = 2 k-steps = 8 LDS.128) with ONE
// isolated change: the two quad-mins inside the body are merged with one
// FMNMX and the (best, pair) accumulator is updated ONCE per body
// (12 -> 8 alu slots per point per body).
// Index recovery, both stages bit-exact:
//   stage 1: recompute the 2 quad-mins of the winning pair with the
//            identical ffma2/fminf sequence, k descending -> earliest k;
//   stage 2: scalar 4-position rescan inside that quad (scan 3..0) ->
//            smallest m. Strict < across pairs keeps the earliest pair ->
//            exact first-index tie-break at every level. Cross-slice/lane
//            merges compare (value, then m).
// Lane layout: q = lane>>3 (one of 4 interleaved M-slices, vector v = 4k+q,
// conflict-free LDS); sub = lane&7; 4 points per thread.
// Comparison key: t = |y|^2/2 - x.y (argmin-equivalent; |x|^2 const/point).
// ---------------------------------------------------------------------------
__global__ void __launch_bounds__(128)
ipgr_persist_kernel(const float* __restrict__ pred,
                    const float* __restrict__ partial,
                    float* __restrict__ out) {
    // SoA tile of partial: yx | yy | yz | yh(=0.5*|y|^2), each MM floats.
    __shared__ __align__(16) float sm[4 * MM];
    __shared__ float smax[4];
    __shared__ float s_mx;

    const int b = blockIdx.y;
    const float* p = partial + (size_t)b * MM * 3;

    for (int m = threadIdx.x; m < MM; m += 128) {
        float yx = p[m * 3 + 0];
        float yy = p[m * 3 + 1];
        float yz = p[m * 3 + 2];
        sm[m]          = yx;
        sm[MM + m]     = yy;
        sm[2 * MM + m] = yz;
        sm[3 * MM + m] = 0.5f * fmaf(yz, yz, fmaf(yy, yy, yx * yx));
    }

    const int lane = threadIdx.x & 31;
    const int warp = threadIdx.x >> 5;
    const int q    = lane >> 3;        // 4 interleaved M-slices
    const int sub  = lane & 7;
    const int n0   = blockIdx.x * 128 + warp * 32 + sub * 4;  // 4 points/thread

    // Refined state lives in registers across iterations.
    float x0[4], x1[4], x2[4];
    {
        const float* rp = pred + ((size_t)b * NN + n0) * 3;
#pragma unroll
        for (int i = 0; i < 4; i++) {
            x0[i] = rp[i * 3 + 0];
            x1[i] = rp[i * 3 + 1];
            x2[i] = rp[i * 3 + 2];
        }
    }
    __syncthreads();

    const ulonglong2* pyx = reinterpret_cast<const ulonglong2*>(sm)          + q;
    const ulonglong2* pyy = reinterpret_cast<const ulonglong2*>(sm + MM)     + q;
    const ulonglong2* pyz = reinterpret_cast<const ulonglong2*>(sm + 2 * MM) + q;
    const ulonglong2* pyh = reinterpret_cast<const ulonglong2*>(sm + 3 * MM) + q;

    for (int it = 0; it < NUM_ITER; it++) {
        uint64_t xp0[4], xp1[4], xp2[4];
        float xs[4];
#pragma unroll
        for (int i = 0; i < 4; i++) {
            xp0[i] = pack2(-x0[i], -x0[i]);
            xp1[i] = pack2(-x1[i], -x1[i]);
            xp2[i] = pack2(-x2[i], -x2[i]);
            xs[i]  = fmaf(x2[i], x2[i], fmaf(x1[i], x1[i], x0[i] * x0[i]));
        }

        // Per point: best 8-m pair-min value + pair index (64 pairs).
        float best[4] = {3.4e38f, 3.4e38f, 3.4e38f, 3.4e38f};
        int   bp[4]   = {0, 0, 0, 0};

        // One body = 2 k-steps = 8 LDS.128 (identical to R13's unroll-2).
#pragma unroll 1
        for (int kp = 0; kp < 64; kp++) {
            const int kA = 2 * kp;
            const int kB = 2 * kp + 1;
            float qmA[4], qmB[4];
            {
                ulonglong2 vx = pyx[4 * kA];
                ulonglong2 vy = pyy[4 * kA];
                ulonglong2 vz = pyz[4 * kA];
                ulonglong2 vh = pyh[4 * kA];
#pragma unroll
                for (int i = 0; i < 4; i++) {
                    uint64_t t01 = ffma2(xp0[i], vx.x, vh.x);
                    t01 = ffma2(xp1[i], vy.x, t01);
                    t01 = ffma2(xp2[i], vz.x, t01);
                    uint64_t t23 = ffma2(xp0[i], vx.y, vh.y);
                    t23 = ffma2(xp1[i], vy.y, t23);
                    t23 = ffma2(xp2[i], vz.y, t23);
                    float t0, t1, t2, t3;
                    unpack2(t01, t0, t1);
                    unpack2(t23, t2, t3);
                    qmA[i] = fminf(fminf(t0, t1), fminf(t2, t3));
                }
            }
            {
                ulonglong2 vx = pyx[4 * kB];
                ulonglong2 vy = pyy[4 * kB];
                ulonglong2 vz = pyz[4 * kB];
                ulonglong2 vh = pyh[4 * kB];
#pragma unroll
                for (int i = 0; i < 4; i++) {
                    uint64_t t01 = ffma2(xp0[i], vx.x, vh.x);
                    t01 = ffma2(xp1[i], vy.x, t01);
                    t01 = ffma2(xp2[i], vz.x, t01);
                    uint64_t t23 = ffma2(xp0[i], vx.y, vh.y);
                    t23 = ffma2(xp1[i], vy.y, t23);
                    t23 = ffma2(xp2[i], vz.y, t23);
                    float t0, t1, t2, t3;
                    unpack2(t01, t0, t1);
                    unpack2(t23, t2, t3);
                    qmB[i] = fminf(fminf(t0, t1), fminf(t2, t3));
                }
            }
#pragma unroll
            for (int i = 0; i < 4; i++) {
                float gm = fminf(qmA[i], qmB[i]);
                bool c = gm < best[i];   // strict: earliest pair kept
                best[i] = c ? gm : best[i];
                bp[i]   = c ? kp : bp[i];
            }
        }

        // Stage 1: recompute the 2 quad-mins of the winning pair (identical
        // op sequence), k descending -> earliest matching k survives.
        float bv[4];
        int   bm[4];
#pragma unroll
        for (int i = 0; i < 4; i++) {
            int kwin = 2 * bp[i];
#pragma unroll
            for (int kk = 1; kk >= 0; kk--) {
                const int k = 2 * bp[i] + kk;
                ulonglong2 vx = pyx[4 * k];
                ulonglong2 vy = pyy[4 * k];
                ulonglong2 vz = pyz[4 * k];
                ulonglong2 vh = pyh[4 * k];
                uint64_t t01 = ffma2(xp0[i], vx.x, vh.x);
                t01 = ffma2(xp1[i], vy.x, t01);
                t01 = ffma2(xp2[i], vz.x, t01);
                uint64_t t23 = ffma2(xp0[i], vx.y, vh.y);
                t23 = ffma2(xp1[i], vy.y, t23);
                t23 = ffma2(xp2[i], vz.y, t23);
                float t0, t1, t2, t3;
                unpack2(t01, t0, t1);
                unpack2(t23, t2, t3);
                float qmin = fminf(fminf(t0, t1), fminf(t2, t3));
                if (qmin == best[i]) kwin = k;
            }
            // Stage 2: scalar rescan of the 4 positions in quad kwin
            // (bit-exact: scalar fma.rn == each f32x2 lane). Scan 3..0.
            const int m0 = (4 * kwin + q) * 4;
            int pos = 3;
#pragma unroll
            for (int j = 2; j >= 0; j--) {
                int mj = m0 + j;
                float tj = fmaf(-x2[i], sm[2 * MM + mj],
                           fmaf(-x1[i], sm[MM + mj],
                           fmaf(-x0[i], sm[mj], sm[3 * MM + mj])));
                if (tj == best[i]) pos = j;
            }
            bv[i] = best[i];
            bm[i] = m0 + pos;
        }

        // Butterfly merge across the 4 slices (bits 3,4): all lanes end with
        // the merged (value, m) for their 4 points. Tie -> smaller m.
#pragma unroll
        for (int r = 8; r <= 16; r <<= 1) {
#pragma unroll
            for (int i = 0; i < 4; i++) {
                float ob = __shfl_xor_sync(0xffffffffu, bv[i], r);
                int   oi = __shfl_xor_sync(0xffffffffu, bm[i], r);
                if (ob < bv[i] || (ob == bv[i] && oi < bm[i])) { bv[i] = ob; bm[i] = oi; }
            }
        }

        // min_dist per point (identical across q-lanes).
        float md[4];
        float mloc = 0.0f;
#pragma unroll
        for (int i = 0; i < 4; i++) {
            float d2 = fmaf(2.0f, bv[i], xs[i]);
            md[i] = sqrtf(fmaxf(d2, 0.0f));
            mloc = fmaxf(mloc, md[i]);
        }

        // Block max -> one atomicMax per block (md >= 0: int order == float).
#pragma unroll
        for (int o = 16; o > 0; o >>= 1)
            mloc = fmaxf(mloc, __shfl_xor_sync(0xffffffffu, mloc, o));
        if (lane == 0) smax[warp] = mloc;
        __syncthreads();

        const int slot = it * BB + b;
        if (threadIdx.x == 0) {
            float m01 = fmaxf(smax[0], smax[1]);
            float m23 = fmaxf(smax[2], smax[3]);
            atomicMax(&g_maxbits[slot], __float_as_int(fmaxf(m01, m23)));
            __threadfence();  // publish max before arrival
            atomicAdd(&g_arrive[slot], 1);
            while (*(volatile int*)&g_arrive[slot] < BLOCKS_PER_BATCH) { }
            __threadfence();
            s_mx = __int_as_float(__ldcg(&g_maxbits[slot]));
        }
        __syncthreads();
        const float mxp = s_mx + 1e-6f;

        // Register-local blend update (all lanes, same result per point).
#pragma unroll
        for (int i = 0; i < 4; i++) {
            int mi = bm[i];
            float alpha = BASE_ALPHA * (2.0f - md[i] / mxp);
            x0[i] = fmaf(alpha, sm[mi]          - x0[i], x0[i]);
            x1[i] = fmaf(alpha, sm[MM + mi]     - x1[i], x1[i]);
            x2[i] = fmaf(alpha, sm[2 * MM + mi] - x2[i], x2[i]);
        }
    }

    // Final store (q==0 lanes own the write; values identical across q).
    if (q == 0) {
        float* rp = out + ((size_t)b * NN + n0) * 3;
#pragma unroll
        for (int i = 0; i < 4; i++) {
            rp[i * 3 + 0] = x0[i];
            rp[i * 3 + 1] = x1[i];
            rp[i * 3 + 2] = x2[i];
        }
    }
}

// ---------------------------------------------------------------------------
extern "C" void kernel_launch(void* const* d_in, const int* in_sizes, int n_in,
                              void* d_out, int out_size) {
    const float* pred    = (const float*)d_in[0];  // [8, 8192, 3] f32
    const float* partial = (const float*)d_in[1];  // [8, 2048, 3] f32
    float* out = (float*)d_out;                     // [8, 8192, 3] f32

    (void)in_sizes; (void)n_in; (void)out_size;

    ipgr_init_kernel<<<1, 64>>>();

    dim3 grid(NN / 128, BB);  // (64, 8) = 512 blocks, all co-resident
    ipgr_persist_kernel<<<grid, 128>>>(pred, partial, out);
}

// round 17
// speedup vs baseline: 1.2606x; 1.1533x over previous
#include <cuda_runtime.h>
#include <cstdint>

#define BB 8
#define NN 8192
#define MM 2048
#define NUM_ITER 4
#define BASE_ALPHA 0.1f
#define WARPS_PER_BATCH 256   // (NN/128 blocks) * 4 warps

// Per-iter per-batch max bits + per-iter per-batch warp-arrival counters.
__device__ int g_maxbits[NUM_ITER * BB];
__device__ int g_arrive [NUM_ITER * BB];

// ---------------------------------------------------------------------------
// f32x2 packed helpers (Blackwell FFMA2 path, PTX fma.rn.f32x2)
// ---------------------------------------------------------------------------
__device__ __forceinline__ uint64_t pack2(float lo, float hi) {
    uint64_t r;
    asm("mov.b64 %0, {%1, %2};" : "=l"(r) : "f"(lo), "f"(hi));
    return r;
}
__device__ __forceinline__ uint64_t ffma2(uint64_t a, uint64_t b, uint64_t c) {
    uint64_t d;
    asm("fma.rn.f32x2 %0, %1, %2, %3;" : "=l"(d) : "l"(a), "l"(b), "l"(c));
    return d;
}
__device__ __forceinline__ void unpack2(uint64_t v, float& lo, float& hi) {
    asm("mov.b64 {%0, %1}, %2;" : "=f"(lo), "=f"(hi) : "l"(v));
}

// ---------------------------------------------------------------------------
// Init: zero the max slots and barrier counters.
// ---------------------------------------------------------------------------
__global__ void ipgr_init_kernel() {
    int i = threadIdx.x;
    if (i < NUM_ITER * BB) {
        g_maxbits[i] = 0;
        g_arrive[i]  = 0;
    }
}

// ---------------------------------------------------------------------------
// Persistent NN + refine kernel: all NUM_ITER iterations in one launch.
// Mainloop BYTE-IDENTICAL to the proven 127.5us R13 kernel (512 co-resident
// blocks, register-resident points, unroll-2 body = 8 LDS.128, value-only
// quad tournament). Only the per-iteration epilogue changed:
//   WARP-AUTONOMOUS BARRIER — each warp's lane0: atomicMax(batch max) ->
//   fence -> atomicAdd(arrive) -> spin until all 256 warps of the batch
//   arrived -> read max; broadcast via shfl. No smem reduce, no
//   __syncthreads in the iteration loop; warps resume independently.
// Correctness of the barrier: a warp reads g_maxbits[slot] only after all
// 256 warps' atomicMax ops are globally visible (fence before arrive).
// Argmin (R13-proven): strict < on quad-min keeps earliest k = smallest m
// in slice; position in the winning vector recovered by bit-exact scalar
// recomputation (scalar fma.rn == each f32x2 lane), scanning 3..0 ->
// exact first-index tie-break; cross-slice/lane merges compare (value, m).
// Lane layout: q = lane>>3 (one of 4 interleaved M-slices, vector v = 4k+q,
// conflict-free LDS); sub = lane&7; 4 points per thread.
// Comparison key: t = |y|^2/2 - x.y (argmin-equivalent; |x|^2 const/point).
// ---------------------------------------------------------------------------
__global__ void __launch_bounds__(128)
ipgr_persist_kernel(const float* __restrict__ pred,
                    const float* __restrict__ partial,
                    float* __restrict__ out) {
    // SoA tile of partial: yx | yy | yz | yh(=0.5*|y|^2), each MM floats.
    __shared__ __align__(16) float sm[4 * MM];

    const int b = blockIdx.y;
    const float* p = partial + (size_t)b * MM * 3;

    for (int m = threadIdx.x; m < MM; m += 128) {
        float yx = p[m * 3 + 0];
        float yy = p[m * 3 + 1];
        float yz = p[m * 3 + 2];
        sm[m]          = yx;
        sm[MM + m]     = yy;
        sm[2 * MM + m] = yz;
        sm[3 * MM + m] = 0.5f * fmaf(yz, yz, fmaf(yy, yy, yx * yx));
    }

    const int lane = threadIdx.x & 31;
    const int warp = threadIdx.x >> 5;
    const int q    = lane >> 3;        // 4 interleaved M-slices
    const int sub  = lane & 7;
    const int n0   = blockIdx.x * 128 + warp * 32 + sub * 4;  // 4 points/thread

    // Refined state lives in registers across iterations.
    float x0[4], x1[4], x2[4];
    {
        const float* rp = pred + ((size_t)b * NN + n0) * 3;
#pragma unroll
        for (int i = 0; i < 4; i++) {
            x0[i] = rp[i * 3 + 0];
            x1[i] = rp[i * 3 + 1];
            x2[i] = rp[i * 3 + 2];
        }
    }
    __syncthreads();   // tile ready (only sync outside the iteration loop)

    const ulonglong2* pyx = reinterpret_cast<const ulonglong2*>(sm)          + q;
    const ulonglong2* pyy = reinterpret_cast<const ulonglong2*>(sm + MM)     + q;
    const ulonglong2* pyz = reinterpret_cast<const ulonglong2*>(sm + 2 * MM) + q;
    const ulonglong2* pyh = reinterpret_cast<const ulonglong2*>(sm + 3 * MM) + q;

    for (int it = 0; it < NUM_ITER; it++) {
        uint64_t xp0[4], xp1[4], xp2[4];
        float xs[4];
#pragma unroll
        for (int i = 0; i < 4; i++) {
            xp0[i] = pack2(-x0[i], -x0[i]);
            xp1[i] = pack2(-x1[i], -x1[i]);
            xp2[i] = pack2(-x2[i], -x2[i]);
            xs[i]  = fmaf(x2[i], x2[i], fmaf(x1[i], x1[i], x0[i] * x0[i]));
        }

        float best[4] = {3.4e38f, 3.4e38f, 3.4e38f, 3.4e38f};
        int   bk[4]   = {0, 0, 0, 0};

#pragma unroll 2
        for (int k = 0; k < 128; k++) {
            ulonglong2 vx = pyx[4 * k];
            ulonglong2 vy = pyy[4 * k];
            ulonglong2 vz = pyz[4 * k];
            ulonglong2 vh = pyh[4 * k];
#pragma unroll
            for (int i = 0; i < 4; i++) {
                uint64_t t01 = ffma2(xp0[i], vx.x, vh.x);
                t01 = ffma2(xp1[i], vy.x, t01);
                t01 = ffma2(xp2[i], vz.x, t01);
                uint64_t t23 = ffma2(xp0[i], vx.y, vh.y);
                t23 = ffma2(xp1[i], vy.y, t23);
                t23 = ffma2(xp2[i], vz.y, t23);
                float t0, t1, t2, t3;
                unpack2(t01, t0, t1);
                unpack2(t23, t2, t3);
                float qmin = fminf(fminf(t0, t1), fminf(t2, t3));
                bool c = qmin < best[i];   // strict: earliest k kept
                best[i] = c ? qmin : best[i];
                bk[i]   = c ? k    : bk[i];
            }
        }

        // Recover exact position (bit-exact scalar recompute, scan 3..0).
        float bv[4];
        int   bm[4];
#pragma unroll
        for (int i = 0; i < 4; i++) {
            const int m0 = (4 * bk[i] + q) * 4;
            int pos = 3;
#pragma unroll
            for (int j = 2; j >= 0; j--) {
                int mj = m0 + j;
                float tj = fmaf(-x2[i], sm[2 * MM + mj],
                           fmaf(-x1[i], sm[MM + mj],
                           fmaf(-x0[i], sm[mj], sm[3 * MM + mj])));
                if (tj == best[i]) pos = j;
            }
            bv[i] = best[i];
            bm[i] = m0 + pos;
        }

        // Butterfly merge across the 4 slices (bits 3,4): all lanes end with
        // the merged (value, m) for their 4 points. Tie -> smaller m.
#pragma unroll
        for (int r = 8; r <= 16; r <<= 1) {
#pragma unroll
            for (int i = 0; i < 4; i++) {
                float ob = __shfl_xor_sync(0xffffffffu, bv[i], r);
                int   oi = __shfl_xor_sync(0xffffffffu, bm[i], r);
                if (ob < bv[i] || (ob == bv[i] && oi < bm[i])) { bv[i] = ob; bm[i] = oi; }
            }
        }

        // min_dist per point (identical across q-lanes).
        float md[4];
        float mloc = 0.0f;
#pragma unroll
        for (int i = 0; i < 4; i++) {
            float d2 = fmaf(2.0f, bv[i], xs[i]);
            md[i] = sqrtf(fmaxf(d2, 0.0f));
            mloc = fmaxf(mloc, md[i]);
        }

        // Warp max (md >= 0: int order == float), then warp-autonomous
        // global barrier: one atomicMax + arrive per warp; lane0 spins,
        // reads the batch max, and broadcasts it via shfl.
#pragma unroll
        for (int o = 16; o > 0; o >>= 1)
            mloc = fmaxf(mloc, __shfl_xor_sync(0xffffffffu, mloc, o));

        const int slot = it * BB + b;
        int mxbits = 0;
        if (lane == 0) {
            atomicMax(&g_maxbits[slot], __float_as_int(mloc));
            __threadfence();  // publish max before arrival
            atomicAdd(&g_arrive[slot], 1);
            while (*(volatile int*)&g_arrive[slot] < WARPS_PER_BATCH) { }
            __threadfence();
            mxbits = __ldcg(&g_maxbits[slot]);
        }
        mxbits = __shfl_sync(0xffffffffu, mxbits, 0);
        const float mxp = __int_as_float(mxbits) + 1e-6f;

        // Register-local blend update (all lanes, same result per point).
#pragma unroll
        for (int i = 0; i < 4; i++) {
            int mi = bm[i];
            float alpha = BASE_ALPHA * (2.0f - md[i] / mxp);
            x0[i] = fmaf(alpha, sm[mi]          - x0[i], x0[i]);
            x1[i] = fmaf(alpha, sm[MM + mi]     - x1[i], x1[i]);
            x2[i] = fmaf(alpha, sm[2 * MM + mi] - x2[i], x2[i]);
        }
    }

    // Final store (q==0 lanes own the write; values identical across q).
    if (q == 0) {
        float* rp = out + ((size_t)b * NN + n0) * 3;
#pragma unroll
        for (int i = 0; i < 4; i++) {
            rp[i * 3 + 0] = x0[i];
            rp[i * 3 + 1] = x1[i];
            rp[i * 3 + 2] = x2[i];
        }
    }
}

// ---------------------------------------------------------------------------
extern "C" void kernel_launch(void* const* d_in, const int* in_sizes, int n_in,
                              void* d_out, int out_size) {
    const float* pred    = (const float*)d_in[0];  // [8, 8192, 3] f32
    const float* partial = (const float*)d_in[1];  // [8, 2048, 3] f32
    float* out = (float*)d_out;                     // [8, 8192, 3] f32

    (void)in_sizes; (void)n_in; (void)out_size;

    ipgr_init_kernel<<<1, 64>>>();

    dim3 grid(NN / 128, BB);  // (64, 8) = 512 blocks, all co-resident
    ipgr_persist_kernel<<<grid, 128>>>(pred, partial, out);
}